// round 15
// baseline (speedup 1.0000x reference)
#include <cuda_runtime.h>
#include <cuda_fp16.h>
#include <math.h>
#include <stdint.h>

// Problem constants
#define N_NODES   100000
#define N_EDGES   600000
#define N_GRAPHS  1000
#define VOCAB     10000
#define D         128
#define TMG       32               // rows per GROUP tile
#define NGROUP    4                // groups per CTA
#define GW        4                // warps per group
#define ROWB      272              // padded smem row stride in bytes (136 fp16)
#define TILE_B    (128 * ROWB)
#define QUART_B   (32 * ROWB)
#define NT_MLP    512              // 16 warps: 4 groups x 4 warps
#define SCAN_BLK  1024
#define NB_MAX    128

// ---------------- scratch -------------------------------------------------
__device__ __half g_x[N_NODES * D];      // fp16 node features, buffer A
__device__ __half g_y[N_NODES * D];      // buffer B
__device__ __half g_embT[VOCAB * D];     // fp16 transformed embeddings
__device__ float  g_pool[N_GRAPHS * D];
__device__ int    g_cnt[N_NODES];
__device__ int    g_cur[N_NODES];
__device__ int    g_rowptr[N_NODES + 1];
__device__ int    g_adj[N_EDGES];
__device__ int    g_bsum[NB_MAX];
__device__ int    g_boff[NB_MAX];
// fp16 weights, transposed [n][k]; mats 0..2 = conv_w1[L], 3..5 = conv_w2[L]
__device__ __half g_wf[6][D * D];

// ---------------- helpers -------------------------------------------------
__device__ __forceinline__ uint32_t smem_u32(const void* p) {
    uint32_t a;
    asm("{ .reg .u64 t; cvta.to.shared.u64 t, %1; cvt.u32.u64 %0, t; }"
        : "=r"(a) : "l"(p));
    return a;
}

__device__ __forceinline__ void mma16816(float* d, uint32_t a0, uint32_t a1,
                                         uint32_t a2, uint32_t a3,
                                         uint32_t b0, uint32_t b1) {
    asm volatile(
        "mma.sync.aligned.m16n8k16.row.col.f32.f16.f16.f32 "
        "{%0,%1,%2,%3}, {%4,%5,%6,%7}, {%8,%9}, {%0,%1,%2,%3};\n"
        : "+f"(d[0]), "+f"(d[1]), "+f"(d[2]), "+f"(d[3])
        : "r"(a0), "r"(a1), "r"(a2), "r"(a3), "r"(b0), "r"(b1));
}

__device__ __forceinline__ void ldm_x4(uint32_t& r0, uint32_t& r1, uint32_t& r2,
                                       uint32_t& r3, uint32_t addr) {
    asm volatile("ldmatrix.sync.aligned.m8n8.x4.shared.b16 {%0,%1,%2,%3}, [%4];"
                 : "=r"(r0), "=r"(r1), "=r"(r2), "=r"(r3) : "r"(addr));
}

__device__ __forceinline__ void ldm_x2(uint32_t& r0, uint32_t& r1, uint32_t addr) {
    asm volatile("ldmatrix.sync.aligned.m8n8.x2.shared.b16 {%0,%1}, [%2];"
                 : "=r"(r0), "=r"(r1) : "r"(addr));
}

__device__ __forceinline__ void group_bar(int g) {
    asm volatile("bar.sync %0, %1;" :: "r"(g + 1), "r"(GW * 32) : "memory");
}

__device__ __forceinline__ void add_h4(float4& v, uint2 p) {
    float2 a = __half22float2(*(__half2*)&p.x);
    float2 b = __half22float2(*(__half2*)&p.y);
    v.x += a.x; v.y += a.y; v.z += b.x; v.w += b.y;
}

// ---------------- CSR build -------------------------------------------------
__global__ void zero_kernel() {
    int i = blockIdx.x * blockDim.x + threadIdx.x;
    int n = gridDim.x * blockDim.x;
    for (int j = i; j < N_NODES; j += n) g_cnt[j] = 0;
    for (int j = i; j < N_GRAPHS * D; j += n) g_pool[j] = 0.0f;
}

__global__ void hist_kernel(const int* __restrict__ dst, int nE) {
    int i = blockIdx.x * blockDim.x + threadIdx.x;
    if (i < nE) atomicAdd(&g_cnt[dst[i]], 1);
}

__global__ void __launch_bounds__(SCAN_BLK, 1) scanA_kernel(int nNodes) {
    __shared__ int red[SCAN_BLK];
    int i = blockIdx.x * SCAN_BLK + threadIdx.x;
    int v = (i < nNodes) ? g_cnt[i] : 0;
    red[threadIdx.x] = v;
    __syncthreads();
    for (int off = SCAN_BLK / 2; off > 0; off >>= 1) {
        if (threadIdx.x < off) red[threadIdx.x] += red[threadIdx.x + off];
        __syncthreads();
    }
    if (threadIdx.x == 0) g_bsum[blockIdx.x] = red[0];
}

__global__ void __launch_bounds__(NB_MAX, 1) scanB_kernel(int nb) {
    __shared__ int s[NB_MAX];
    int t = threadIdx.x;
    int v = (t < nb) ? g_bsum[t] : 0;
    s[t] = v;
    __syncthreads();
    for (int off = 1; off < NB_MAX; off <<= 1) {
        int u = (t >= off) ? s[t - off] : 0;
        __syncthreads();
        s[t] += u;
        __syncthreads();
    }
    if (t < nb) g_boff[t] = s[t] - v;
}

__global__ void __launch_bounds__(SCAN_BLK, 1) scanC_kernel(int nNodes) {
    __shared__ int s[SCAN_BLK];
    int i = blockIdx.x * SCAN_BLK + threadIdx.x;
    int t = threadIdx.x;
    int v = (i < nNodes) ? g_cnt[i] : 0;
    s[t] = v;
    __syncthreads();
    for (int off = 1; off < SCAN_BLK; off <<= 1) {
        int u = (t >= off) ? s[t - off] : 0;
        __syncthreads();
        s[t] += u;
        __syncthreads();
    }
    if (i < nNodes) {
        int excl = s[t] - v + g_boff[blockIdx.x];
        g_rowptr[i] = excl;
        g_cur[i] = excl;
        if (i == nNodes - 1) g_rowptr[nNodes] = excl + v;
    }
}

__global__ void fill_kernel(const int* __restrict__ src,
                            const int* __restrict__ dst, int nE) {
    int i = blockIdx.x * blockDim.x + threadIdx.x;
    if (i >= nE) return;
    int pos = atomicAdd(&g_cur[dst[i]], 1);
    g_adj[pos] = src[i];
}

// ---------------- weight prep -----------------------------------------------
__global__ void prep_weights(const float* __restrict__ w1,
                             const float* __restrict__ w2) {
    int i = blockIdx.x * blockDim.x + threadIdx.x;
    if (i >= 6 * D * D) return;
    int m = i / (D * D), kn = i % (D * D);
    int k = kn / D, n = kn % D;
    float v = (m < 3) ? w1[m * D * D + kn] : w2[(m - 3) * D * D + kn];
    g_wf[m][n * D + k] = __float2half_rn(v);
}

// ---------------- GEMM phase (per warp: 32x32 patch; single fp16) -----------
__device__ __forceinline__ void gemm_phase(uint32_t aH, uint32_t bH,
                                           float (&acc)[2][4][4]) {
#pragma unroll
    for (int k0 = 0; k0 < D; k0 += 16) {
        uint32_t ah0[2], ah1[2], ah2[2], ah3[2];
        uint32_t bh0[4], bh1[4];
#pragma unroll
        for (int mt = 0; mt < 2; ++mt)
            ldm_x4(ah0[mt], ah1[mt], ah2[mt], ah3[mt], aH + mt * (16 * ROWB) + k0 * 2);
#pragma unroll
        for (int nt = 0; nt < 4; ++nt)
            ldm_x2(bh0[nt], bh1[nt], bH + nt * (8 * ROWB) + k0 * 2);
#pragma unroll
        for (int mt = 0; mt < 2; ++mt)
#pragma unroll
            for (int nt = 0; nt < 4; ++nt)
                mma16816(acc[mt][nt], ah0[mt], ah1[mt], ah2[mt], ah3[mt], bh0[nt], bh1[nt]);
    }
}

// ---- batched CSR gather over fp16 rows: v += sum rows[idx(j)] --------------
__device__ __forceinline__ float4 gather_sum_h(const __half* __restrict__ rows,
                                               const int* __restrict__ xidx,
                                               int e0, int e1, int c4, float4 v) {
    int j = e0;
    for (; j + 4 <= e1; j += 4) {
        int n0 = g_adj[j], n1 = g_adj[j + 1], n2 = g_adj[j + 2], n3 = g_adj[j + 3];
        if (xidx) { n0 = xidx[n0]; n1 = xidx[n1]; n2 = xidx[n2]; n3 = xidx[n3]; }
        uint2 u0 = *(const uint2*)(rows + (size_t)n0 * D + c4);
        uint2 u1 = *(const uint2*)(rows + (size_t)n1 * D + c4);
        uint2 u2 = *(const uint2*)(rows + (size_t)n2 * D + c4);
        uint2 u3 = *(const uint2*)(rows + (size_t)n3 * D + c4);
        add_h4(v, u0); add_h4(v, u1); add_h4(v, u2); add_h4(v, u3);
    }
    int rem = e1 - j;
    uint2 u0, u1, u2;
    if (rem > 0) {
        int n0 = g_adj[j];
        if (xidx) n0 = xidx[n0];
        u0 = *(const uint2*)(rows + (size_t)n0 * D + c4);
    }
    if (rem > 1) {
        int n1 = g_adj[j + 1];
        if (xidx) n1 = xidx[n1];
        u1 = *(const uint2*)(rows + (size_t)n1 * D + c4);
    }
    if (rem > 2) {
        int n2 = g_adj[j + 2];
        if (xidx) n2 = xidx[n2];
        u2 = *(const uint2*)(rows + (size_t)n2 * D + c4);
    }
    if (rem > 0) add_h4(v, u0);
    if (rem > 1) add_h4(v, u1);
    if (rem > 2) add_h4(v, u2);
    return v;
}

// ---------------- persistent fused aggregate+MLP, 4 groups per CTA ----------
// MODE 0: out = xf @ W[w2_id]                      (fp32 in, fp16 out)
// MODE 1: A = sum embT[x_idx[self+nbrs]]; h = relu(A + b1); out = relu(h@W2 + b2)
// MODE 2: A = xh[self] + sum xh[nbrs]; h = relu(A@W1 + b1); out = relu(h@W2 + b2)
// pbatch != nullptr: red.add fp32 result into g_pool[batch[row]] instead of out.
template <int MODE>
__global__ void __launch_bounds__(NT_MLP, 1)
mlp_mma(const float* __restrict__ xf, const __half* __restrict__ xh,
        const int* __restrict__ xidx, int w1_id, int w2_id,
        const float* __restrict__ b1, const float* __restrict__ b2,
        __half* __restrict__ out, const int* __restrict__ pbatch,
        int nRows, int nTiles) {
    extern __shared__ __align__(16) unsigned char sm[];
    unsigned char* Ah = sm;                  // 128 rows: group g owns rows [32g, 32g+32)
    unsigned char* W2 = sm + TILE_B;
    unsigned char* W1 = sm + 2 * TILE_B;     // MODE 2 only
    __shared__ float b1s[D], b2s[D];

    const int tid  = threadIdx.x;
    const int lane = tid & 31, wid = tid >> 5;
    const int g    = wid >> 2;               // group 0..3
    const int wg   = wid & 3;                // warp within group
    const int N0 = wg * 32;

    if (MODE != 0 && tid < D) {
        b2s[tid] = b2[tid];
        if (MODE == 2) b1s[tid] = b1[tid];
    }

    // stage weights once (all 16 warps); fp16 tables
    {
        const uint4* s2 = (const uint4*)g_wf[w2_id];
        for (int i = tid; i < 128 * 16; i += NT_MLP) {
            int n = i >> 4, c = i & 15;
            *(uint4*)(W2 + n * ROWB + c * 16) = s2[n * 16 + c];
        }
        if (MODE == 2) {
            const uint4* s1 = (const uint4*)g_wf[w1_id];
            for (int i = tid; i < 128 * 16; i += NT_MLP) {
                int n = i >> 4, c = i & 15;
                *(uint4*)(W1 + n * ROWB + c * 16) = s1[n * 16 + c];
            }
        }
    }
    __syncthreads();

    unsigned char* AhG = Ah + g * QUART_B;
    const uint32_t aOff = (uint32_t)(lane & 15) * ROWB + ((lane >> 4) * 16);
    const uint32_t bOff = (uint32_t)(N0 + (lane & 7)) * ROWB + (((lane >> 3) & 1) * 16);
    const uint32_t aH = smem_u32(AhG) + aOff;
    const uint32_t w2H = smem_u32(W2) + bOff;
    const uint32_t w1H = (MODE == 2) ? smem_u32(W1) + bOff : 0;

    for (int t = blockIdx.x * NGROUP + g; t < nTiles; t += gridDim.x * NGROUP) {
        const int row0 = t * TMG;
        group_bar(g);

        // ---- fused aggregate + fp16 convert of A quarter (warp per row) ----
        for (int rr = wg; rr < TMG; rr += GW) {
            const int gr = row0 + rr;
            float4 v = make_float4(0.f, 0.f, 0.f, 0.f);
            if (gr < nRows) {
                const int c4 = lane * 4;
                if (MODE == 0) {
                    v = *(const float4*)(xf + (size_t)gr * D + c4);
                } else if (MODE == 1) {
                    int self = xidx[gr];
                    int e0 = g_rowptr[gr], e1 = g_rowptr[gr + 1];
                    add_h4(v, *(const uint2*)(g_embT + (size_t)self * D + c4));
                    v = gather_sum_h(g_embT, xidx, e0, e1, c4, v);
                    float4 bv = *(const float4*)(b1 + c4);
                    v.x = fmaxf(v.x + bv.x, 0.f); v.y = fmaxf(v.y + bv.y, 0.f);
                    v.z = fmaxf(v.z + bv.z, 0.f); v.w = fmaxf(v.w + bv.w, 0.f);
                } else {
                    int e0 = g_rowptr[gr], e1 = g_rowptr[gr + 1];
                    add_h4(v, *(const uint2*)(xh + (size_t)gr * D + c4));
                    v = gather_sum_h(xh, nullptr, e0, e1, c4, v);
                }
            }
            __half2 p01; p01.x = __float2half_rn(v.x); p01.y = __float2half_rn(v.y);
            __half2 p23; p23.x = __float2half_rn(v.z); p23.y = __float2half_rn(v.w);
            *(uint2*)(AhG + rr * ROWB + lane * 8) =
                make_uint2(*(uint32_t*)&p01, *(uint32_t*)&p23);
        }
        group_bar(g);

        float acc[2][4][4];

        if (MODE == 2) {
            // phase 1: h = relu(A @ W1 + b1) -> back into AhG
#pragma unroll
            for (int nt = 0; nt < 4; ++nt) {
                int c = N0 + nt * 8 + (lane & 3) * 2;
                float bb0 = b1s[c], bb1 = b1s[c + 1];
#pragma unroll
                for (int mt = 0; mt < 2; ++mt) {
                    acc[mt][nt][0] = bb0; acc[mt][nt][1] = bb1;
                    acc[mt][nt][2] = bb0; acc[mt][nt][3] = bb1;
                }
            }
            gemm_phase(aH, w1H, acc);
            group_bar(g);
#pragma unroll
            for (int mt = 0; mt < 2; ++mt) {
#pragma unroll
                for (int nt = 0; nt < 4; ++nt) {
                    int r = mt * 16 + (lane >> 2);
                    int c = N0 + nt * 8 + (lane & 3) * 2;
                    float v0 = fmaxf(acc[mt][nt][0], 0.f), v1 = fmaxf(acc[mt][nt][1], 0.f);
                    float v2 = fmaxf(acc[mt][nt][2], 0.f), v3 = fmaxf(acc[mt][nt][3], 0.f);
                    __half2 p01; p01.x = __float2half_rn(v0); p01.y = __float2half_rn(v1);
                    __half2 p23; p23.x = __float2half_rn(v2); p23.y = __float2half_rn(v3);
                    *(uint32_t*)(AhG + r * ROWB + c * 2)       = *(uint32_t*)&p01;
                    *(uint32_t*)(AhG + (r + 8) * ROWB + c * 2) = *(uint32_t*)&p23;
                }
            }
            group_bar(g);
        }

        // phase 2
        if (MODE == 0) {
#pragma unroll
            for (int mt = 0; mt < 2; ++mt)
#pragma unroll
                for (int nt = 0; nt < 4; ++nt)
                    acc[mt][nt][0] = acc[mt][nt][1] = acc[mt][nt][2] = acc[mt][nt][3] = 0.f;
        } else {
#pragma unroll
            for (int nt = 0; nt < 4; ++nt) {
                int c = N0 + nt * 8 + (lane & 3) * 2;
                float bb0 = b2s[c], bb1 = b2s[c + 1];
#pragma unroll
                for (int mt = 0; mt < 2; ++mt) {
                    acc[mt][nt][0] = bb0; acc[mt][nt][1] = bb1;
                    acc[mt][nt][2] = bb0; acc[mt][nt][3] = bb1;
                }
            }
        }
        gemm_phase(aH, w2H, acc);

        // ---- epilogue ----
#pragma unroll
        for (int mt = 0; mt < 2; ++mt) {
            int r = row0 + mt * 16 + (lane >> 2);
            int bi0 = 0, bi8 = 0;
            if (pbatch) {
                if (r < nRows)     bi0 = pbatch[r];
                if (r + 8 < nRows) bi8 = pbatch[r + 8];
            }
#pragma unroll
            for (int nt = 0; nt < 4; ++nt) {
                int c = N0 + nt * 8 + (lane & 3) * 2;
                float v0 = acc[mt][nt][0], v1 = acc[mt][nt][1];
                float v2 = acc[mt][nt][2], v3 = acc[mt][nt][3];
                if (MODE != 0) {
                    v0 = fmaxf(v0, 0.f); v1 = fmaxf(v1, 0.f);
                    v2 = fmaxf(v2, 0.f); v3 = fmaxf(v3, 0.f);
                }
                if (pbatch) {
                    if (r < nRows) {
                        float* p = g_pool + bi0 * D + c;
                        asm volatile("red.global.add.v2.f32 [%0], {%1, %2};"
                                     :: "l"(p), "f"(v0), "f"(v1) : "memory");
                    }
                    if (r + 8 < nRows) {
                        float* p = g_pool + bi8 * D + c;
                        asm volatile("red.global.add.v2.f32 [%0], {%1, %2};"
                                     :: "l"(p), "f"(v2), "f"(v3) : "memory");
                    }
                } else {
                    if (r < nRows) {
                        __half2 p; p.x = __float2half_rn(v0); p.y = __float2half_rn(v1);
                        *(uint32_t*)(out + (size_t)r * D + c) = *(uint32_t*)&p;
                    }
                    if (r + 8 < nRows) {
                        __half2 p; p.x = __float2half_rn(v2); p.y = __float2half_rn(v3);
                        *(uint32_t*)(out + (size_t)(r + 8) * D + c) = *(uint32_t*)&p;
                    }
                }
            }
        }
    }
}

// ---------------- classifier ------------------------------------------------
__global__ void classifier_kernel(const int* __restrict__ batch, int nNodes,
                                  const float* __restrict__ w1,
                                  const float* __restrict__ b1,
                                  const float* __restrict__ w2,
                                  const float* __restrict__ b2,
                                  float* __restrict__ out) {
    __shared__ float gs[D];
    __shared__ float hs[64];
    __shared__ float cnt_s;
    const int b = blockIdx.x;
    const int t = threadIdx.x;

    if (t == 0) {
        int lo = 0, hi = nNodes;
        while (lo < hi) { int m = (lo + hi) >> 1; if (batch[m] < b) lo = m + 1; else hi = m; }
        int start = lo;
        lo = start; hi = nNodes;
        while (lo < hi) { int m = (lo + hi) >> 1; if (batch[m] <= b) lo = m + 1; else hi = m; }
        cnt_s = fmaxf((float)(lo - start), 1.0f);
    }
    __syncthreads();

    gs[t] = g_pool[b * D + t] / cnt_s;
    __syncthreads();

    if (t < 64) {
        float h = b1[t];
#pragma unroll 8
        for (int k = 0; k < D; ++k) h += gs[k] * w1[k * 64 + t];
        hs[t] = fmaxf(h, 0.f);
    }
    __syncthreads();

    if (t == 0) {
        float o0 = b2[0], o1 = b2[1];
#pragma unroll 8
        for (int j = 0; j < 64; ++j) {
            o0 += hs[j] * w2[2 * j];
            o1 += hs[j] * w2[2 * j + 1];
        }
        float m = fmaxf(o0, o1);
        float e0 = expf(o0 - m), e1 = expf(o1 - m);
        float s = e0 + e1;
        out[2 * b]     = e0 / s;
        out[2 * b + 1] = e1 / s;
    }
}

// ---------------------------------------------------------------------------
extern "C" void kernel_launch(void* const* d_in, const int* in_sizes, int n_in,
                              void* d_out, int out_size) {
    const int*   x_idx   = (const int*)d_in[0];
    const int*   edge    = (const int*)d_in[1];
    const int*   batch   = (const int*)d_in[2];
    const float* emb     = (const float*)d_in[3];
    const float* conv_w1 = (const float*)d_in[4];
    const float* conv_b1 = (const float*)d_in[5];
    const float* conv_w2 = (const float*)d_in[6];
    const float* conv_b2 = (const float*)d_in[7];
    const float* mlp_w1  = (const float*)d_in[8];
    const float* mlp_b1  = (const float*)d_in[9];
    const float* mlp_w2  = (const float*)d_in[10];
    const float* mlp_b2  = (const float*)d_in[11];
    float* out = (float*)d_out;

    const int nNodes = in_sizes[0];
    const int nEdges = in_sizes[1] / 2;
    const int nVocab = in_sizes[3] / D;
    const int* src = edge;
    const int* dst = edge + nEdges;

    __half *px, *py, *pembT;
    cudaGetSymbolAddress((void**)&px,    g_x);
    cudaGetSymbolAddress((void**)&py,    g_y);
    cudaGetSymbolAddress((void**)&pembT, g_embT);

    const int smem_small = 2 * TILE_B;   // 69632
    const int smem_big   = 3 * TILE_B;   // 104448
    cudaFuncSetAttribute(mlp_mma<0>, cudaFuncAttributeMaxDynamicSharedMemorySize, smem_small);
    cudaFuncSetAttribute(mlp_mma<1>, cudaFuncAttributeMaxDynamicSharedMemorySize, smem_small);
    cudaFuncSetAttribute(mlp_mma<2>, cudaFuncAttributeMaxDynamicSharedMemorySize, smem_big);

    const int nodeTiles = (nNodes + TMG - 1) / TMG;    // 32-row tiles
    const int embTiles  = (nVocab + TMG - 1) / TMG;
    const int grid1 = (nodeTiles + NGROUP - 1) / NGROUP < 148
                          ? (nodeTiles + NGROUP - 1) / NGROUP : 148;
    const int gridE = (embTiles + NGROUP - 1) / NGROUP < 148
                          ? (embTiles + NGROUP - 1) / NGROUP : 148;
    const int nb = (nNodes + SCAN_BLK - 1) / SCAN_BLK;

    // CSR build + zeros + weight prep
    zero_kernel<<<256, 256>>>();
    prep_weights<<<(6 * D * D + 255) / 256, 256>>>(conv_w1, conv_w2);
    hist_kernel<<<(nEdges + 255) / 256, 256>>>(dst, nEdges);
    scanA_kernel<<<nb, SCAN_BLK>>>(nNodes);
    scanB_kernel<<<1, NB_MAX>>>(nb);
    scanC_kernel<<<nb, SCAN_BLK>>>(nNodes);
    fill_kernel<<<(nEdges + 255) / 256, 256>>>(src, dst, nEdges);

    // embT = emb @ conv_w1[0]   (fp32 in -> fp16 out)
    mlp_mma<0><<<gridE, NT_MLP, smem_small>>>(emb, nullptr, nullptr, -1, 0,
                                              nullptr, nullptr, pembT, nullptr,
                                              nVocab, embTiles);

    // layer 0 (fused gather + aggregate): embT[x_idx] pull -> px
    mlp_mma<1><<<grid1, NT_MLP, smem_small>>>(nullptr, pembT, x_idx, -1, 3,
                                              conv_b1, conv_b2, px, nullptr,
                                              nNodes, nodeTiles);

    // layer 1: px -> py
    mlp_mma<2><<<grid1, NT_MLP, smem_big>>>(nullptr, px, nullptr, 1, 4,
                                            conv_b1 + D, conv_b2 + D, py, nullptr,
                                            nNodes, nodeTiles);

    // layer 2: py -> pooled sums
    mlp_mma<2><<<grid1, NT_MLP, smem_big>>>(nullptr, py, nullptr, 2, 5,
                                            conv_b1 + 2 * D, conv_b2 + 2 * D,
                                            nullptr, batch, nNodes, nodeTiles);

    // classifier + softmax
    classifier_kernel<<<N_GRAPHS, D>>>(batch, nNodes, mlp_w1, mlp_b1, mlp_w2,
                                       mlp_b2, out);
}

// round 17
// speedup vs baseline: 1.3694x; 1.3694x over previous
#include <cuda_runtime.h>
#include <cuda_fp16.h>
#include <math.h>
#include <stdint.h>

// Problem constants
#define N_NODES   100000
#define N_EDGES   600000
#define N_GRAPHS  1000
#define VOCAB     10000
#define D         128
#define TMG       32               // rows per GROUP tile
#define NGROUP    4                // groups per CTA
#define GW        4                // warps per group
#define ROWB      272              // padded smem row stride in bytes (136 fp16)
#define TILE_B    (128 * ROWB)
#define QUART_B   (32 * ROWB)
#define NT_MLP    512              // 16 warps: 4 groups x 4 warps
#define SCAN_BLK  1024
#define NB_MAX    128

// ---------------- scratch -------------------------------------------------
__device__ __half g_x[N_NODES * D];
__device__ __half g_y[N_NODES * D];
__device__ __half g_embT[VOCAB * D];
__device__ float  g_pool[N_GRAPHS * D];
__device__ int    g_cnt[N_NODES];
__device__ int    g_cur[N_NODES];
__device__ int    g_rowptr[N_NODES + 1];
__device__ int    g_adj[N_EDGES];
__device__ int    g_bsum[NB_MAX];
// fp16 weights, transposed [n][k]; mats 0..2 = conv_w1[L], 3..5 = conv_w2[L]
__device__ __half g_wf[6][D * D];

// ---------------- helpers -------------------------------------------------
__device__ __forceinline__ uint32_t smem_u32(const void* p) {
    uint32_t a;
    asm("{ .reg .u64 t; cvta.to.shared.u64 t, %1; cvt.u32.u64 %0, t; }"
        : "=r"(a) : "l"(p));
    return a;
}

__device__ __forceinline__ void mma16816(float* d, uint32_t a0, uint32_t a1,
                                         uint32_t a2, uint32_t a3,
                                         uint32_t b0, uint32_t b1) {
    asm volatile(
        "mma.sync.aligned.m16n8k16.row.col.f32.f16.f16.f32 "
        "{%0,%1,%2,%3}, {%4,%5,%6,%7}, {%8,%9}, {%0,%1,%2,%3};\n"
        : "+f"(d[0]), "+f"(d[1]), "+f"(d[2]), "+f"(d[3])
        : "r"(a0), "r"(a1), "r"(a2), "r"(a3), "r"(b0), "r"(b1));
}

__device__ __forceinline__ void ldm_x4(uint32_t& r0, uint32_t& r1, uint32_t& r2,
                                       uint32_t& r3, uint32_t addr) {
    asm volatile("ldmatrix.sync.aligned.m8n8.x4.shared.b16 {%0,%1,%2,%3}, [%4];"
                 : "=r"(r0), "=r"(r1), "=r"(r2), "=r"(r3) : "r"(addr));
}

__device__ __forceinline__ void ldm_x2(uint32_t& r0, uint32_t& r1, uint32_t addr) {
    asm volatile("ldmatrix.sync.aligned.m8n8.x2.shared.b16 {%0,%1}, [%2];"
                 : "=r"(r0), "=r"(r1) : "r"(addr));
}

__device__ __forceinline__ void group_bar(int g) {
    asm volatile("bar.sync %0, %1;" :: "r"(g + 1), "r"(GW * 32) : "memory");
}

// add 8 packed halfs into acc[0..7]
__device__ __forceinline__ void acc8(float* a, uint4 u) {
    __half2* h = (__half2*)&u;
#pragma unroll
    for (int k = 0; k < 4; ++k) {
        float2 f = __half22float2(h[k]);
        a[2 * k] += f.x;
        a[2 * k + 1] += f.y;
    }
}

// ---------------- CSR build -------------------------------------------------
__global__ void zero_kernel() {
    int i = blockIdx.x * blockDim.x + threadIdx.x;
    int n = gridDim.x * blockDim.x;
    for (int j = i; j < N_NODES; j += n) g_cnt[j] = 0;
    for (int j = i; j < N_GRAPHS * D; j += n) g_pool[j] = 0.0f;
}

__global__ void hist_kernel(const int* __restrict__ dst, int nE) {
    int i = blockIdx.x * blockDim.x + threadIdx.x;
    if (i < nE) atomicAdd(&g_cnt[dst[i]], 1);
}

__global__ void __launch_bounds__(SCAN_BLK, 1) scanA_kernel(int nNodes) {
    __shared__ int red[SCAN_BLK];
    int i = blockIdx.x * SCAN_BLK + threadIdx.x;
    int v = (i < nNodes) ? g_cnt[i] : 0;
    red[threadIdx.x] = v;
    __syncthreads();
    for (int off = SCAN_BLK / 2; off > 0; off >>= 1) {
        if (threadIdx.x < off) red[threadIdx.x] += red[threadIdx.x + off];
        __syncthreads();
    }
    if (threadIdx.x == 0) g_bsum[blockIdx.x] = red[0];
}

// merged: per-block scan + block-offset computed from g_bsum directly
__global__ void __launch_bounds__(SCAN_BLK, 1) scanC_kernel(int nNodes, int nb) {
    __shared__ int s[SCAN_BLK];
    __shared__ int boff;
    int i = blockIdx.x * SCAN_BLK + threadIdx.x;
    int t = threadIdx.x;
    if (t == 0) {
        int sum = 0;
        for (int b = 0; b < blockIdx.x; ++b) sum += g_bsum[b];
        boff = sum;
    }
    int v = (i < nNodes) ? g_cnt[i] : 0;
    s[t] = v;
    __syncthreads();
    for (int off = 1; off < SCAN_BLK; off <<= 1) {
        int u = (t >= off) ? s[t - off] : 0;
        __syncthreads();
        s[t] += u;
        __syncthreads();
    }
    if (i < nNodes) {
        int excl = s[t] - v + boff;
        g_rowptr[i] = excl;
        g_cur[i] = excl;
        if (i == nNodes - 1) g_rowptr[nNodes] = excl + v;
    }
}

__global__ void fill_kernel(const int* __restrict__ src,
                            const int* __restrict__ dst, int nE) {
    int i = blockIdx.x * blockDim.x + threadIdx.x;
    if (i >= nE) return;
    int pos = atomicAdd(&g_cur[dst[i]], 1);
    g_adj[pos] = src[i];
}

// ---------------- weight prep -----------------------------------------------
__global__ void prep_weights(const float* __restrict__ w1,
                             const float* __restrict__ w2) {
    int i = blockIdx.x * blockDim.x + threadIdx.x;
    if (i >= 6 * D * D) return;
    int m = i / (D * D), kn = i % (D * D);
    int k = kn / D, n = kn % D;
    float v = (m < 3) ? w1[m * D * D + kn] : w2[(m - 3) * D * D + kn];
    g_wf[m][n * D + k] = __float2half_rn(v);
}

// ---------------- GEMM phase (per warp: 32x32 patch; single fp16) -----------
__device__ __forceinline__ void gemm_phase(uint32_t aH, uint32_t bH,
                                           float (&acc)[2][4][4]) {
#pragma unroll
    for (int k0 = 0; k0 < D; k0 += 16) {
        uint32_t ah0[2], ah1[2], ah2[2], ah3[2];
        uint32_t bh0[4], bh1[4];
#pragma unroll
        for (int mt = 0; mt < 2; ++mt)
            ldm_x4(ah0[mt], ah1[mt], ah2[mt], ah3[mt], aH + mt * (16 * ROWB) + k0 * 2);
#pragma unroll
        for (int nt = 0; nt < 4; ++nt)
            ldm_x2(bh0[nt], bh1[nt], bH + nt * (8 * ROWB) + k0 * 2);
#pragma unroll
        for (int mt = 0; mt < 2; ++mt)
#pragma unroll
            for (int nt = 0; nt < 4; ++nt)
                mma16816(acc[mt][nt], ah0[mt], ah1[mt], ah2[mt], ah3[mt], bh0[nt], bh1[nt]);
    }
}

// ---------------- persistent fused aggregate+MLP, 4 groups per CTA ----------
// MODE 0: out = xf @ W[w2_id]                      (fp32 in, fp16 out)
// MODE 1: A = sum embT[x_idx[self+nbrs]]; h = relu(A + b1); out = relu(h@W2 + b2)
// MODE 2: A = xh[self] + sum xh[nbrs]; h = relu(A@W1 + b1); out = relu(h@W2 + b2)
// pbatch != nullptr: red.add fp32 result into g_pool[batch[row]] instead of out.
template <int MODE>
__global__ void __launch_bounds__(NT_MLP, 1)
mlp_mma(const float* __restrict__ xf, const __half* __restrict__ xh,
        const int* __restrict__ xidx, int w1_id, int w2_id,
        const float* __restrict__ b1, const float* __restrict__ b2,
        __half* __restrict__ out, const int* __restrict__ pbatch,
        int nRows, int nTiles) {
    extern __shared__ __align__(16) unsigned char sm[];
    unsigned char* Ah = sm;                  // 128 rows: group g owns rows [32g, 32g+32)
    unsigned char* W2 = sm + TILE_B;
    unsigned char* W1 = sm + 2 * TILE_B;     // MODE 2 only
    __shared__ float b1s[D], b2s[D];

    const int tid  = threadIdx.x;
    const int lane = tid & 31, wid = tid >> 5;
    const int g    = wid >> 2;               // group 0..3
    const int wg   = wid & 3;                // warp within group
    const int N0 = wg * 32;

    if (MODE != 0 && tid < D) {
        b2s[tid] = b2[tid];
        b1s[tid] = b1[tid];      // FIX: b1s needed by MODE 1 aggregation too
    }

    // stage weights once (all 16 warps); fp16 tables
    {
        const uint4* s2 = (const uint4*)g_wf[w2_id];
        for (int i = tid; i < 128 * 16; i += NT_MLP) {
            int n = i >> 4, c = i & 15;
            *(uint4*)(W2 + n * ROWB + c * 16) = s2[n * 16 + c];
        }
        if (MODE == 2) {
            const uint4* s1 = (const uint4*)g_wf[w1_id];
            for (int i = tid; i < 128 * 16; i += NT_MLP) {
                int n = i >> 4, c = i & 15;
                *(uint4*)(W1 + n * ROWB + c * 16) = s1[n * 16 + c];
            }
        }
    }
    __syncthreads();

    unsigned char* AhG = Ah + g * QUART_B;
    const uint32_t aOff = (uint32_t)(lane & 15) * ROWB + ((lane >> 4) * 16);
    const uint32_t bOff = (uint32_t)(N0 + (lane & 7)) * ROWB + (((lane >> 3) & 1) * 16);
    const uint32_t aH = smem_u32(AhG) + aOff;
    const uint32_t w2H = smem_u32(W2) + bOff;
    const uint32_t w1H = (MODE == 2) ? smem_u32(W1) + bOff : 0;

    for (int t = blockIdx.x * NGROUP + g; t < nTiles; t += gridDim.x * NGROUP) {
        const int row0 = t * TMG;
        group_bar(g);

        // ---- fused aggregate: 8 lanes per row, 4 rows concurrent ----
        if (MODE == 0) {
            for (int rr = wg; rr < TMG; rr += GW) {
                const int gr = row0 + rr;
                float4 v = make_float4(0.f, 0.f, 0.f, 0.f);
                if (gr < nRows) v = *(const float4*)(xf + (size_t)gr * D + lane * 4);
                __half2 p01; p01.x = __float2half_rn(v.x); p01.y = __float2half_rn(v.y);
                __half2 p23; p23.x = __float2half_rn(v.z); p23.y = __float2half_rn(v.w);
                *(uint2*)(AhG + rr * ROWB + lane * 8) =
                    make_uint2(*(uint32_t*)&p01, *(uint32_t*)&p23);
            }
        } else {
            const __half* rows = (MODE == 1) ? g_embT : xh;
            const int q = lane & 7;            // 8 lanes per row
            const int c16 = q * 16;            // 16 halfs per lane slice
#pragma unroll
            for (int s = 0; s < 2; ++s) {      // two row-sets of 4 rows
                const int rr = wg * 8 + s * 4 + (lane >> 3);
                const int gr = row0 + rr;
                float acc16[16];
#pragma unroll
                for (int i = 0; i < 16; ++i) acc16[i] = 0.f;
                if (gr < nRows) {
                    int e0 = g_rowptr[gr], e1 = g_rowptr[gr + 1];
                    // self
                    {
                        int self = (MODE == 1) ? xidx[gr] : gr;
                        const __half* rp = rows + (size_t)self * D + c16;
                        acc8(acc16, *(const uint4*)rp);
                        acc8(acc16 + 8, *(const uint4*)(rp + 8));
                    }
                    int j = e0;
                    for (; j + 4 <= e1; j += 4) {
                        int n0 = g_adj[j], n1 = g_adj[j + 1];
                        int n2 = g_adj[j + 2], n3 = g_adj[j + 3];
                        if (MODE == 1) {
                            n0 = xidx[n0]; n1 = xidx[n1];
                            n2 = xidx[n2]; n3 = xidx[n3];
                        }
                        const __half* r0 = rows + (size_t)n0 * D + c16;
                        const __half* r1 = rows + (size_t)n1 * D + c16;
                        const __half* r2 = rows + (size_t)n2 * D + c16;
                        const __half* r3 = rows + (size_t)n3 * D + c16;
                        uint4 a0 = *(const uint4*)r0, b0 = *(const uint4*)(r0 + 8);
                        uint4 a1 = *(const uint4*)r1, b1v = *(const uint4*)(r1 + 8);
                        uint4 a2 = *(const uint4*)r2, b2v = *(const uint4*)(r2 + 8);
                        uint4 a3 = *(const uint4*)r3, b3 = *(const uint4*)(r3 + 8);
                        acc8(acc16, a0); acc8(acc16 + 8, b0);
                        acc8(acc16, a1); acc8(acc16 + 8, b1v);
                        acc8(acc16, a2); acc8(acc16 + 8, b2v);
                        acc8(acc16, a3); acc8(acc16 + 8, b3);
                    }
                    for (; j < e1; ++j) {
                        int n0 = g_adj[j];
                        if (MODE == 1) n0 = xidx[n0];
                        const __half* r0 = rows + (size_t)n0 * D + c16;
                        acc8(acc16, *(const uint4*)r0);
                        acc8(acc16 + 8, *(const uint4*)(r0 + 8));
                    }
                    if (MODE == 1) {
#pragma unroll
                        for (int i = 0; i < 16; ++i)
                            acc16[i] = fmaxf(acc16[i] + b1s[c16 + i], 0.f);
                    }
                }
                // convert to fp16 and store 32B slice
                uint4 o0, o1;
                __half2* ph = (__half2*)&o0;
#pragma unroll
                for (int k = 0; k < 4; ++k) {
                    __half2 p; p.x = __float2half_rn(acc16[2 * k]);
                    p.y = __float2half_rn(acc16[2 * k + 1]);
                    ph[k] = p;
                }
                ph = (__half2*)&o1;
#pragma unroll
                for (int k = 0; k < 4; ++k) {
                    __half2 p; p.x = __float2half_rn(acc16[8 + 2 * k]);
                    p.y = __float2half_rn(acc16[8 + 2 * k + 1]);
                    ph[k] = p;
                }
                *(uint4*)(AhG + rr * ROWB + q * 32) = o0;
                *(uint4*)(AhG + rr * ROWB + q * 32 + 16) = o1;
            }
        }
        group_bar(g);

        float acc[2][4][4];

        if (MODE == 2) {
            // phase 1: h = relu(A @ W1 + b1) -> back into AhG
#pragma unroll
            for (int nt = 0; nt < 4; ++nt) {
                int c = N0 + nt * 8 + (lane & 3) * 2;
                float bb0 = b1s[c], bb1 = b1s[c + 1];
#pragma unroll
                for (int mt = 0; mt < 2; ++mt) {
                    acc[mt][nt][0] = bb0; acc[mt][nt][1] = bb1;
                    acc[mt][nt][2] = bb0; acc[mt][nt][3] = bb1;
                }
            }
            gemm_phase(aH, w1H, acc);
            group_bar(g);
#pragma unroll
            for (int mt = 0; mt < 2; ++mt) {
#pragma unroll
                for (int nt = 0; nt < 4; ++nt) {
                    int r = mt * 16 + (lane >> 2);
                    int c = N0 + nt * 8 + (lane & 3) * 2;
                    float v0 = fmaxf(acc[mt][nt][0], 0.f), v1 = fmaxf(acc[mt][nt][1], 0.f);
                    float v2 = fmaxf(acc[mt][nt][2], 0.f), v3 = fmaxf(acc[mt][nt][3], 0.f);
                    __half2 p01; p01.x = __float2half_rn(v0); p01.y = __float2half_rn(v1);
                    __half2 p23; p23.x = __float2half_rn(v2); p23.y = __float2half_rn(v3);
                    *(uint32_t*)(AhG + r * ROWB + c * 2)       = *(uint32_t*)&p01;
                    *(uint32_t*)(AhG + (r + 8) * ROWB + c * 2) = *(uint32_t*)&p23;
                }
            }
            group_bar(g);
        }

        // phase 2
        if (MODE == 0) {
#pragma unroll
            for (int mt = 0; mt < 2; ++mt)
#pragma unroll
                for (int nt = 0; nt < 4; ++nt)
                    acc[mt][nt][0] = acc[mt][nt][1] = acc[mt][nt][2] = acc[mt][nt][3] = 0.f;
        } else {
#pragma unroll
            for (int nt = 0; nt < 4; ++nt) {
                int c = N0 + nt * 8 + (lane & 3) * 2;
                float bb0 = b2s[c], bb1 = b2s[c + 1];
#pragma unroll
                for (int mt = 0; mt < 2; ++mt) {
                    acc[mt][nt][0] = bb0; acc[mt][nt][1] = bb1;
                    acc[mt][nt][2] = bb0; acc[mt][nt][3] = bb1;
                }
            }
        }
        gemm_phase(aH, w2H, acc);

        // ---- epilogue ----
#pragma unroll
        for (int mt = 0; mt < 2; ++mt) {
            int r = row0 + mt * 16 + (lane >> 2);
            int bi0 = 0, bi8 = 0;
            if (pbatch) {
                if (r < nRows)     bi0 = pbatch[r];
                if (r + 8 < nRows) bi8 = pbatch[r + 8];
            }
#pragma unroll
            for (int nt = 0; nt < 4; ++nt) {
                int c = N0 + nt * 8 + (lane & 3) * 2;
                float v0 = acc[mt][nt][0], v1 = acc[mt][nt][1];
                float v2 = acc[mt][nt][2], v3 = acc[mt][nt][3];
                if (MODE != 0) {
                    v0 = fmaxf(v0, 0.f); v1 = fmaxf(v1, 0.f);
                    v2 = fmaxf(v2, 0.f); v3 = fmaxf(v3, 0.f);
                }
                if (pbatch) {
                    if (r < nRows) {
                        float* p = g_pool + bi0 * D + c;
                        asm volatile("red.global.add.v2.f32 [%0], {%1, %2};"
                                     :: "l"(p), "f"(v0), "f"(v1) : "memory");
                    }
                    if (r + 8 < nRows) {
                        float* p = g_pool + bi8 * D + c;
                        asm volatile("red.global.add.v2.f32 [%0], {%1, %2};"
                                     :: "l"(p), "f"(v2), "f"(v3) : "memory");
                    }
                } else {
                    if (r < nRows) {
                        __half2 p; p.x = __float2half_rn(v0); p.y = __float2half_rn(v1);
                        *(uint32_t*)(out + (size_t)r * D + c) = *(uint32_t*)&p;
                    }
                    if (r + 8 < nRows) {
                        __half2 p; p.x = __float2half_rn(v2); p.y = __float2half_rn(v3);
                        *(uint32_t*)(out + (size_t)(r + 8) * D + c) = *(uint32_t*)&p;
                    }
                }
            }
        }
    }
}

// ---------------- classifier ------------------------------------------------
__global__ void classifier_kernel(const int* __restrict__ batch, int nNodes,
                                  const float* __restrict__ w1,
                                  const float* __restrict__ b1,
                                  const float* __restrict__ w2,
                                  const float* __restrict__ b2,
                                  float* __restrict__ out) {
    __shared__ float gs[D];
    __shared__ float hs[64];
    __shared__ float cnt_s;
    const int b = blockIdx.x;
    const int t = threadIdx.x;

    if (t == 0) {
        int lo = 0, hi = nNodes;
        while (lo < hi) { int m = (lo + hi) >> 1; if (batch[m] < b) lo = m + 1; else hi = m; }
        int start = lo;
        lo = start; hi = nNodes;
        while (lo < hi) { int m = (lo + hi) >> 1; if (batch[m] <= b) lo = m + 1; else hi = m; }
        cnt_s = fmaxf((float)(lo - start), 1.0f);
    }
    __syncthreads();

    gs[t] = g_pool[b * D + t] / cnt_s;
    __syncthreads();

    if (t < 64) {
        float h = b1[t];
#pragma unroll 8
        for (int k = 0; k < D; ++k) h += gs[k] * w1[k * 64 + t];
        hs[t] = fmaxf(h, 0.f);
    }
    __syncthreads();

    if (t == 0) {
        float o0 = b2[0], o1 = b2[1];
#pragma unroll 8
        for (int j = 0; j < 64; ++j) {
            o0 += hs[j] * w2[2 * j];
            o1 += hs[j] * w2[2 * j + 1];
        }
        float m = fmaxf(o0, o1);
        float e0 = expf(o0 - m), e1 = expf(o1 - m);
        float s = e0 + e1;
        out[2 * b]     = e0 / s;
        out[2 * b + 1] = e1 / s;
    }
}

// ---------------------------------------------------------------------------
extern "C" void kernel_launch(void* const* d_in, const int* in_sizes, int n_in,
                              void* d_out, int out_size) {
    const int*   x_idx   = (const int*)d_in[0];
    const int*   edge    = (const int*)d_in[1];
    const int*   batch   = (const int*)d_in[2];
    const float* emb     = (const float*)d_in[3];
    const float* conv_w1 = (const float*)d_in[4];
    const float* conv_b1 = (const float*)d_in[5];
    const float* conv_w2 = (const float*)d_in[6];
    const float* conv_b2 = (const float*)d_in[7];
    const float* mlp_w1  = (const float*)d_in[8];
    const float* mlp_b1  = (const float*)d_in[9];
    const float* mlp_w2  = (const float*)d_in[10];
    const float* mlp_b2  = (const float*)d_in[11];
    float* out = (float*)d_out;

    const int nNodes = in_sizes[0];
    const int nEdges = in_sizes[1] / 2;
    const int nVocab = in_sizes[3] / D;
    const int* src = edge;
    const int* dst = edge + nEdges;

    __half *px, *py, *pembT;
    cudaGetSymbolAddress((void**)&px,    g_x);
    cudaGetSymbolAddress((void**)&py,    g_y);
    cudaGetSymbolAddress((void**)&pembT, g_embT);

    const int smem_small = 2 * TILE_B;   // 69632
    const int smem_big   = 3 * TILE_B;   // 104448
    cudaFuncSetAttribute(mlp_mma<0>, cudaFuncAttributeMaxDynamicSharedMemorySize, smem_small);
    cudaFuncSetAttribute(mlp_mma<1>, cudaFuncAttributeMaxDynamicSharedMemorySize, smem_small);
    cudaFuncSetAttribute(mlp_mma<2>, cudaFuncAttributeMaxDynamicSharedMemorySize, smem_big);

    const int nodeTiles = (nNodes + TMG - 1) / TMG;    // 32-row tiles
    const int embTiles  = (nVocab + TMG - 1) / TMG;
    const int grid1 = (nodeTiles + NGROUP - 1) / NGROUP < 148
                          ? (nodeTiles + NGROUP - 1) / NGROUP : 148;
    const int gridE = (embTiles + NGROUP - 1) / NGROUP < 148
                          ? (embTiles + NGROUP - 1) / NGROUP : 148;
    const int nb = (nNodes + SCAN_BLK - 1) / SCAN_BLK;

    zero_kernel<<<256, 256>>>();
    hist_kernel<<<(nEdges + 255) / 256, 256>>>(dst, nEdges);
    prep_weights<<<(6 * D * D + 255) / 256, 256>>>(conv_w1, conv_w2);

    // embT = emb @ conv_w1[0]   (fp32 in -> fp16 out)
    mlp_mma<0><<<gridE, NT_MLP, smem_small>>>(emb, nullptr, nullptr, -1, 0,
                                              nullptr, nullptr, pembT, nullptr,
                                              nVocab, embTiles);

    scanA_kernel<<<nb, SCAN_BLK>>>(nNodes);
    scanC_kernel<<<nb, SCAN_BLK>>>(nNodes, nb);
    fill_kernel<<<(nEdges + 255) / 256, 256>>>(src, dst, nEdges);

    // layer 0 (fused gather + aggregate): embT[x_idx] pull -> px
    mlp_mma<1><<<grid1, NT_MLP, smem_small>>>(nullptr, pembT, x_idx, -1, 3,
                                              conv_b1, conv_b2, px, nullptr,
                                              nNodes, nodeTiles);

    // layer 1: px -> py
    mlp_mma<2><<<grid1, NT_MLP, smem_big>>>(nullptr, px, nullptr, 1, 4,
                                            conv_b1 + D, conv_b2 + D, py, nullptr,
                                            nNodes, nodeTiles);

    // layer 2: py -> pooled sums
    mlp_mma<2><<<grid1, NT_MLP, smem_big>>>(nullptr, py, nullptr, 2, 5,
                                            conv_b1 + 2 * D, conv_b2 + 2 * D,
                                            nullptr, batch, nNodes, nodeTiles);

    // classifier + softmax
    classifier_kernel<<<N_GRAPHS, D>>>(batch, nNodes, mlp_w1, mlp_b1, mlp_w2,
                                       mlp_b2, out);
}